// round 8
// baseline (speedup 1.0000x reference)
#include <cuda_runtime.h>
#include <cstdint>

#define Hh   128
#define Ww   240
#define NG   40
#define CPG  8
#define ND   48
#define NCC  12
#define WQ   60

#define GWC_CTAS (NG * Hh)                // 5120
#define CAT_CTAS (Hh * ND)                // 6144
#define TOTAL_CTAS (GWC_CTAS + CAT_CTAS)  // 11264 = 1024 * 11

#define ROWB (CPG * Ww * 4)               // 7680B staged row

__device__ __forceinline__ uint32_t sw128(uint32_t b) {
    return b ^ ((b >> 3) & 0x70);
}

__device__ __forceinline__ unsigned long long pack_f2(float lo, float hi) {
    unsigned long long r;
    asm("mov.b64 %0, {%1, %2};" : "=l"(r) : "f"(lo), "f"(hi));
    return r;
}

// ---------------------------------------------------------------------------
// GWC: out[g][d][h][w] = (1/8) sum_c ref[gc][h][w] * tgt[gc][h][w-d]
// 64-thread CTA per (g,h); thread owns 4 consecutive w (threads 60-63 clamp
// and compute redundantly, store-masked). 4-slot sliding register window,
// software-pipelined refill (next-d LDS issued before current-d FMA chain).
// ---------------------------------------------------------------------------
__device__ __forceinline__ void gwc_part(
    unsigned char* smem, int g, int h, int tid,
    const float* __restrict__ refg, const float* __restrict__ tgtg,
    float* __restrict__ out)
{
    // Stage tgt row: transposed [w][c], SW128-swizzled (32B per w).
    {
        const float* tb = tgtg + ((size_t)(g * CPG) * Hh + h) * Ww;
        for (int i = tid; i < CPG * WQ; i += 64) {
            int cc = i / WQ;
            int q  = i - cc * WQ;
            float4 v = *(const float4*)(tb + (size_t)cc * Hh * Ww + 4 * q);
            float vv[4] = {v.x, v.y, v.z, v.w};
#pragma unroll
            for (int j = 0; j < 4; j++)
                *(float*)(smem + sw128((uint32_t)((4 * q + j) * 32 + cc * 4))) = vv[j];
        }
    }

    const bool act = (tid < WQ);
    const int  q   = act ? tid : (WQ - 1);     // clamp; no divergent exit
    const int  wb  = 4 * q;

    // rt64[j][p] = (ref[c=2p](wb+j), ref[c=2p+1](wb+j)) / 8, packed f32x2.
    unsigned long long rt64[4][4];
    {
        const float* rb = refg + ((size_t)(g * CPG) * Hh + h) * Ww + wb;
        float4 rch[8];
#pragma unroll
        for (int cc = 0; cc < 8; cc++)
            rch[cc] = *(const float4*)(rb + (size_t)cc * Hh * Ww);
#pragma unroll
        for (int p = 0; p < 4; p++) {
            const float4 e = rch[2 * p], o = rch[2 * p + 1];
            rt64[0][p] = pack_f2(e.x * 0.125f, o.x * 0.125f);
            rt64[1][p] = pack_f2(e.y * 0.125f, o.y * 0.125f);
            rt64[2][p] = pack_f2(e.z * 0.125f, o.z * 0.125f);
            rt64[3][p] = pack_f2(e.w * 0.125f, o.w * 0.125f);
        }
    }
    __syncthreads();

    // Invariant: win[(j - d) & 3] holds tgt[wb + j - d][0..7] as 4 c-pairs.
    ulonglong2 win[4][2];
#pragma unroll
    for (int k = 0; k < 4; k++) {
        uint32_t b = (uint32_t)((wb + k) * 32);
        win[k][0] = *(const ulonglong2*)(smem + sw128(b));
        win[k][1] = *(const ulonglong2*)(smem + sw128(b + 16));
    }

    float* op = out + (((size_t)g * ND) * Hh + h) * Ww + wb;
#pragma unroll
    for (int d = 0; d < ND; d++) {
        // ---- prefetch next-d position into temps (hides LDS latency) ----
        ulonglong2 nw0 = make_ulonglong2(0ull, 0ull);
        ulonglong2 nw1 = make_ulonglong2(0ull, 0ull);
        if (d < ND - 1) {
            const int wp = wb - d - 1;
            if (wp >= 0) {
                uint32_t b = (uint32_t)(wp * 32);
                nw0 = *(const ulonglong2*)(smem + sw128(b));
                nw1 = *(const ulonglong2*)(smem + sw128(b + 16));
            }
        }

        // ---- compute 4 outputs ----
        float a[4];
#pragma unroll
        for (int j = 0; j < 4; j++) {
            const int k = (j - d) & 3;
            unsigned long long acc;
            asm("mul.rn.f32x2 %0, %1, %2;"
                : "=l"(acc) : "l"(rt64[j][0]), "l"(win[k][0].x));
            asm("fma.rn.f32x2 %0, %1, %2, %3;"
                : "=l"(acc) : "l"(rt64[j][1]), "l"(win[k][0].y), "l"(acc));
            asm("fma.rn.f32x2 %0, %1, %2, %3;"
                : "=l"(acc) : "l"(rt64[j][2]), "l"(win[k][1].x), "l"(acc));
            asm("fma.rn.f32x2 %0, %1, %2, %3;"
                : "=l"(acc) : "l"(rt64[j][3]), "l"(win[k][1].y), "l"(acc));
            float lo, hi;
            asm("mov.b64 {%0, %1}, %2;" : "=f"(lo), "=f"(hi) : "l"(acc));
            a[j] = lo + hi;
        }
        if (act) {
            float4 o; o.x = a[0]; o.y = a[1]; o.z = a[2]; o.w = a[3];
            *(float4*)op = o;
        }
        op += (size_t)Hh * Ww;

        // ---- commit prefetched position ----
        if (d < ND - 1) {
            const int slot = (3 - d) & 3;
            win[slot][0] = nw0;
            win[slot][1] = nw1;
        }
    }
}

// ---------------------------------------------------------------------------
// Concat: 64-thread CTA per (h, d). Thread owns chunk q, covers all 24 out
// channels: 40..51 = ref masked (w>=d), 52..63 = tgt shifted right by d.
// Shift s = d&3 is CTA-uniform -> template, static funnel selects.
// ---------------------------------------------------------------------------
template <int S>
__device__ __forceinline__ void cat_inner(
    int h, int d, int t,
    const float* __restrict__ rc, const float* __restrict__ tc,
    float* __restrict__ out)
{
    if (t >= WQ) return;
    const int q  = t;
    const int a  = d >> 2;
    const int wb = 4 * q;
    const size_t hw = (size_t)Hh * Ww;
    float* ob = out + ((size_t)NG * ND + (size_t)d) * hw + (size_t)h * Ww + wb;

#pragma unroll
    for (int cc = 0; cc < NCC; cc++) {
        // ref channel cc, masked where w < d
        float4 v = *(const float4*)(rc + ((size_t)cc * Hh + h) * Ww + wb);
        float4 o;
        o.x = (wb + 0 >= d) ? v.x : 0.f;
        o.y = (wb + 1 >= d) ? v.y : 0.f;
        o.z = (wb + 2 >= d) ? v.z : 0.f;
        o.w = (wb + 3 >= d) ? v.w : 0.f;
        *(float4*)(ob + (size_t)cc * ND * hw) = o;

        // tgt channel cc, shifted right by d
        const float* row = tc + ((size_t)cc * Hh + h) * Ww;
        const int c1 = q - a, c0 = q - a - 1;
        float4 v1 = (c1 >= 0) ? *(const float4*)(row + 4 * c1)
                              : make_float4(0.f, 0.f, 0.f, 0.f);
        float4 v0 = (c0 >= 0) ? *(const float4*)(row + 4 * c0)
                              : make_float4(0.f, 0.f, 0.f, 0.f);
        float4 s;
        if (S == 0)      { s = v1; }
        else if (S == 1) { s.x = v0.w; s.y = v1.x; s.z = v1.y; s.w = v1.z; }
        else if (S == 2) { s.x = v0.z; s.y = v0.w; s.z = v1.x; s.w = v1.y; }
        else             { s.x = v0.y; s.y = v0.z; s.z = v0.w; s.w = v1.x; }
        *(float4*)(ob + (size_t)(NCC + cc) * ND * hw) = s;
    }
}

// ---------------------------------------------------------------------------
__global__ void __launch_bounds__(64) fused_kernel(
    const float* __restrict__ refg, const float* __restrict__ tgtg,
    const float* __restrict__ rc,   const float* __restrict__ tc,
    float* __restrict__ out)
{
    __shared__ __align__(16) unsigned char smem[ROWB];  // 7680B

    const int bx  = blockIdx.x;
    const int tid = threadIdx.x;
    const int qq  = bx / 11;
    const int r   = bx - qq * 11;

    if (r < 5) {
        const int idx = qq * 5 + r;          // 0..5119
        gwc_part(smem, idx / Hh, idx % Hh, tid, refg, tgtg, out);
    } else {
        const int idx = qq * 6 + (r - 5);    // 0..6143
        const int d = idx / Hh;
        const int h = idx % Hh;
        switch (d & 3) {
            case 0: cat_inner<0>(h, d, tid, rc, tc, out); break;
            case 1: cat_inner<1>(h, d, tid, rc, tc, out); break;
            case 2: cat_inner<2>(h, d, tid, rc, tc, out); break;
            default: cat_inner<3>(h, d, tid, rc, tc, out); break;
        }
    }
}

extern "C" void kernel_launch(void* const* d_in, const int* in_sizes, int n_in,
                              void* d_out, int out_size)
{
    const float* refg = (const float*)d_in[0];  // ref_gwc    [320,128,240]
    const float* tgtg = (const float*)d_in[1];  // tgt_gwc    [320,128,240]
    const float* rc   = (const float*)d_in[2];  // ref_concat [12,128,240]
    const float* tc   = (const float*)d_in[3];  // tgt_concat [12,128,240]
    float* out = (float*)d_out;                 // [64,48,128,240]

    fused_kernel<<<TOTAL_CTAS, 64>>>(refg, tgtg, rc, tc, out);
}

// round 9
// speedup vs baseline: 1.1302x; 1.1302x over previous
#include <cuda_runtime.h>
#include <cstdint>

#define Hh   128
#define Ww   240
#define NG   40
#define CPG  8
#define ND   48
#define NCC  12
#define WQ   60

#define GWC_CTAS (NG * Hh)            // 5120
#define CAT_CTAS (Hh * ND)            // 6144
#define TOTAL_CTAS (GWC_CTAS + CAT_CTAS)  // 11264 = 1024 * 11

__device__ __forceinline__ uint32_t sw128(uint32_t b) {
    return b ^ ((b >> 3) & 0x70);
}

__device__ __forceinline__ unsigned long long pack_f2(float lo, float hi) {
    unsigned long long r;
    asm("mov.b64 %0, {%1, %2};" : "=l"(r) : "f"(lo), "f"(hi));
    return r;
}

// ---------------------------------------------------------------------------
// GWC: out[g][d][h][w] = (1/8) sum_c ref[gc][h][w] * tgt[gc][h][w-d]
// 128-thread CTA per (g,h); thread owns 2 consecutive w. Packed f32x2 FMA.
// 2-slot sliding register window over d (1 new position = 2 LDS.128 per d).
// ---------------------------------------------------------------------------
__device__ __forceinline__ void gwc_part(
    unsigned char* smem, int g, int h, int tid,
    const float* __restrict__ refg, const float* __restrict__ tgtg,
    float* __restrict__ out)
{
    // Stage tgt group-row: SMEM transposed [w][c], SW128-swizzled (32B per w).
    {
        const float* tb = tgtg + ((size_t)(g * CPG) * Hh + h) * Ww;
        for (int i = tid; i < CPG * WQ; i += 128) {
            int cc = i / WQ;
            int q  = i - cc * WQ;
            float4 v = *(const float4*)(tb + (size_t)cc * Hh * Ww + 4 * q);
            float vv[4] = {v.x, v.y, v.z, v.w};
#pragma unroll
            for (int j = 0; j < 4; j++)
                *(float*)(smem + sw128((uint32_t)((4 * q + j) * 32 + cc * 4))) = vv[j];
        }
    }

    const int  t   = tid;
    const bool act = (t < 120);

    // rt64[j][p] = (ref[c=2p](w=2t+j), ref[c=2p+1](w=2t+j)) * 1/8, packed f32x2.
    unsigned long long rt64[2][4];
    if (act) {
        const float* rb = refg + ((size_t)(g * CPG) * Hh + h) * Ww + 2 * t;
        float2 rch[8];
#pragma unroll
        for (int cc = 0; cc < 8; cc++)
            rch[cc] = *(const float2*)(rb + (size_t)cc * Hh * Ww);
#pragma unroll
        for (int p = 0; p < 4; p++) {
            rt64[0][p] = pack_f2(rch[2 * p].x * 0.125f, rch[2 * p + 1].x * 0.125f);
            rt64[1][p] = pack_f2(rch[2 * p].y * 0.125f, rch[2 * p + 1].y * 0.125f);
        }
    }
    __syncthreads();
    if (!act) return;

    // Invariant: win[(j - d) & 1] holds tgt[2t + j - d][0..7] as 4 c-pairs.
    ulonglong2 win[2][2];
#pragma unroll
    for (int k = 0; k < 2; k++) {
        uint32_t b = (uint32_t)((2 * t + k) * 32);
        win[k][0] = *(const ulonglong2*)(smem + sw128(b));
        win[k][1] = *(const ulonglong2*)(smem + sw128(b + 16));
    }

    // Running refill byte offset: position (2t - d - 1) at step d.
    int rb_off = (2 * t - 1) * 32;

    float* op = out + (((size_t)g * ND) * Hh + h) * Ww + 2 * t;
#pragma unroll
    for (int d = 0; d < ND; d++) {
        float2 o;
#pragma unroll
        for (int j = 0; j < 2; j++) {
            const int k = (j - d) & 1;
            unsigned long long acc;
            asm("mul.rn.f32x2 %0, %1, %2;"
                : "=l"(acc) : "l"(rt64[j][0]), "l"(win[k][0].x));
            asm("fma.rn.f32x2 %0, %1, %2, %3;"
                : "=l"(acc) : "l"(rt64[j][1]), "l"(win[k][0].y), "l"(acc));
            asm("fma.rn.f32x2 %0, %1, %2, %3;"
                : "=l"(acc) : "l"(rt64[j][2]), "l"(win[k][1].x), "l"(acc));
            asm("fma.rn.f32x2 %0, %1, %2, %3;"
                : "=l"(acc) : "l"(rt64[j][3]), "l"(win[k][1].y), "l"(acc));
            float lo, hi;
            asm("mov.b64 {%0, %1}, %2;" : "=f"(lo), "=f"(hi) : "l"(acc));
            if (j == 0) o.x = lo + hi; else o.y = lo + hi;
        }
        *(float2*)op = o;
        op += (size_t)Hh * Ww;

        if (d < ND - 1) {
            const int slot = (d + 1) & 1;
            if (rb_off >= 0) {
                win[slot][0] = *(const ulonglong2*)(smem + sw128((uint32_t)rb_off));
                win[slot][1] = *(const ulonglong2*)(smem + sw128((uint32_t)rb_off + 16));
            } else {
                win[slot][0] = make_ulonglong2(0ull, 0ull);
                win[slot][1] = make_ulonglong2(0ull, 0ull);
            }
            rb_off -= 32;
        }
    }
}

// ---------------------------------------------------------------------------
// Concat: CTA per (h, d). Channels 40..51 = ref masked (w>=d),
// 52..63 = tgt shifted right by d. Funnel-shift of two aligned float4 loads;
// shift s = d&3 is CTA-uniform -> template instantiation, static selects.
// ---------------------------------------------------------------------------
template <int S>
__device__ __forceinline__ void cat_inner(
    int h, int d, int t,
    const float* __restrict__ rc, const float* __restrict__ tc,
    float* __restrict__ out)
{
    if (t >= 120) return;
    const int half = (t >= 60) ? 1 : 0;
    const int q    = t - 60 * half;
    const int a    = d >> 2;
    const int wb   = 4 * q;
    const size_t hw = (size_t)Hh * Ww;

#pragma unroll
    for (int i = 0; i < 12; i++) {
        const int cc = half + 2 * i;      // 0..23
        float4 o;
        if (i < 6) {
            // ref channel cc, masked where w < d
            float4 v = *(const float4*)(rc + ((size_t)cc * Hh + h) * Ww + wb);
            o.x = (wb + 0 >= d) ? v.x : 0.f;
            o.y = (wb + 1 >= d) ? v.y : 0.f;
            o.z = (wb + 2 >= d) ? v.z : 0.f;
            o.w = (wb + 3 >= d) ? v.w : 0.f;
        } else {
            // tgt channel cc-12, shifted right by d
            const int ch = cc - NCC;
            const float* row = tc + ((size_t)ch * Hh + h) * Ww;
            const int c1 = q - a, c0 = q - a - 1;
            float4 v1 = (c1 >= 0) ? *(const float4*)(row + 4 * c1)
                                  : make_float4(0.f, 0.f, 0.f, 0.f);
            float4 v0 = (c0 >= 0) ? *(const float4*)(row + 4 * c0)
                                  : make_float4(0.f, 0.f, 0.f, 0.f);
            if (S == 0)      { o = v1; }
            else if (S == 1) { o.x = v0.w; o.y = v1.x; o.z = v1.y; o.w = v1.z; }
            else if (S == 2) { o.x = v0.z; o.y = v0.w; o.z = v1.x; o.w = v1.y; }
            else             { o.x = v0.y; o.y = v0.z; o.z = v0.w; o.w = v1.x; }
        }
        *(float4*)(out + ((size_t)(NG + cc) * ND + d) * hw + h * Ww + wb) = o;
    }
}

// ---------------------------------------------------------------------------
__global__ void __launch_bounds__(128, 10) fused_kernel(
    const float* __restrict__ refg, const float* __restrict__ tgtg,
    const float* __restrict__ rc,   const float* __restrict__ tc,
    float* __restrict__ out)
{
    __shared__ __align__(16) unsigned char smem[CPG * Ww * 4];  // 7680B

    const int bx  = blockIdx.x;
    const int tid = threadIdx.x;
    const int qq  = bx / 11;
    const int r   = bx - qq * 11;

    if (r < 5) {
        const int idx = qq * 5 + r;          // 0..5119
        gwc_part(smem, idx / Hh, idx % Hh, tid, refg, tgtg, out);
    } else {
        const int idx = qq * 6 + (r - 5);    // 0..6143
        const int d = idx / Hh;
        const int h = idx % Hh;
        switch (d & 3) {
            case 0: cat_inner<0>(h, d, tid, rc, tc, out); break;
            case 1: cat_inner<1>(h, d, tid, rc, tc, out); break;
            case 2: cat_inner<2>(h, d, tid, rc, tc, out); break;
            default: cat_inner<3>(h, d, tid, rc, tc, out); break;
        }
    }
}

extern "C" void kernel_launch(void* const* d_in, const int* in_sizes, int n_in,
                              void* d_out, int out_size)
{
    const float* refg = (const float*)d_in[0];  // ref_gwc    [320,128,240]
    const float* tgtg = (const float*)d_in[1];  // tgt_gwc    [320,128,240]
    const float* rc   = (const float*)d_in[2];  // ref_concat [12,128,240]
    const float* tc   = (const float*)d_in[3];  // tgt_concat [12,128,240]
    float* out = (float*)d_out;                 // [64,48,128,240]

    fused_kernel<<<TOTAL_CTAS, 128>>>(refg, tgtg, rc, tc, out);
}

// round 10
// speedup vs baseline: 1.1808x; 1.0448x over previous
#include <cuda_runtime.h>
#include <cstdint>

#define Hh   128
#define Ww   240
#define NG   40
#define CPG  8
#define ND   48
#define NCC  12
#define WQ   60

#define PSTRIDE 40                         // bytes per position in SMEM (8ch*4B + 8 pad)
#define GWC_CTAS (NG * Hh)                 // 5120
#define CAT_CTAS (Hh * (ND / 4))           // 1536 (d-groups of 4)
#define TOTAL_CTAS (GWC_CTAS + CAT_CTAS)   // 6656 = 512 * 13

// ---------------------------------------------------------------------------
// GWC: out[g][d][h][w] = (1/8) sum_c ref[gc][h][w] * tgt[gc][h][w-d]
// 128-thread CTA per (g,h); thread owns 2 consecutive w. Packed f32x2 FMA.
// SMEM tgt layout: position p at byte 40p, channels 0..7 at +4c.
// 40B stride => lane addresses (80B apart) spread across banks: conflict-free
// LDS.64 window reads AND conflict-free cc-major STS.32 staging.
// ---------------------------------------------------------------------------
__device__ __forceinline__ void gwc_part(
    unsigned char* smem, int g, int h, int tid,
    const float* __restrict__ refg, const float* __restrict__ tgtg,
    float* __restrict__ out)
{
    // Stage tgt group-row. cc-major: lanes 0-7 cover the 8 channels of one
    // 4-w chunk -> STS.32 hits 32 distinct banks; LDG spans 8 rows x 64B
    // contiguous = 16 sectors per warp (same as coalesced).
    {
        const float* tb = tgtg + ((size_t)(g * CPG) * Hh + h) * Ww;
        for (int i = tid; i < CPG * WQ; i += 128) {
            int cc = i & 7;
            int q  = i >> 3;
            float4 v = *(const float4*)(tb + (size_t)cc * Hh * Ww + 4 * q);
            unsigned char* base = smem + cc * 4 + PSTRIDE * 4 * q;
            *(float*)(base + 0 * PSTRIDE) = v.x;
            *(float*)(base + 1 * PSTRIDE) = v.y;
            *(float*)(base + 2 * PSTRIDE) = v.z;
            *(float*)(base + 3 * PSTRIDE) = v.w;
        }
    }

    const int  t   = tid;
    const bool act = (t < 120);

    // rt64[j][p] = (ref[c=2p](w=2t+j), ref[c=2p+1](w=2t+j)) * 1/8, packed f32x2.
    unsigned long long rt64[2][4];
    if (act) {
        const float* rb = refg + ((size_t)(g * CPG) * Hh + h) * Ww + 2 * t;
        float2 rch[8];
#pragma unroll
        for (int cc = 0; cc < 8; cc++)
            rch[cc] = *(const float2*)(rb + (size_t)cc * Hh * Ww);
#pragma unroll
        for (int p = 0; p < 4; p++) {
            float2 lo = make_float2(rch[2 * p].x * 0.125f, rch[2 * p + 1].x * 0.125f);
            float2 hi = make_float2(rch[2 * p].y * 0.125f, rch[2 * p + 1].y * 0.125f);
            asm("mov.b64 %0, {%1, %2};" : "=l"(rt64[0][p]) : "f"(lo.x), "f"(lo.y));
            asm("mov.b64 %0, {%1, %2};" : "=l"(rt64[1][p]) : "f"(hi.x), "f"(hi.y));
        }
    }
    __syncthreads();
    if (!act) return;

    // Invariant: win[(j - d) & 1][p] = f32x2 pair p of tgt[2t + j - d].
    unsigned long long win[2][4];
#pragma unroll
    for (int k = 0; k < 2; k++) {
        const unsigned char* base = smem + PSTRIDE * (2 * t + k);
#pragma unroll
        for (int p = 0; p < 4; p++)
            win[k][p] = *(const unsigned long long*)(base + 8 * p);
    }

    // Running refill byte offset: position (2t - d - 1) at step d.
    int rb_off = (2 * t - 1) * PSTRIDE;

    float* op = out + (((size_t)g * ND) * Hh + h) * Ww + 2 * t;
#pragma unroll
    for (int d = 0; d < ND; d++) {
        float2 o;
#pragma unroll
        for (int j = 0; j < 2; j++) {
            const int k = (j - d) & 1;
            unsigned long long acc;
            asm("mul.rn.f32x2 %0, %1, %2;"
                : "=l"(acc) : "l"(rt64[j][0]), "l"(win[k][0]));
            asm("fma.rn.f32x2 %0, %1, %2, %3;"
                : "=l"(acc) : "l"(rt64[j][1]), "l"(win[k][1]), "l"(acc));
            asm("fma.rn.f32x2 %0, %1, %2, %3;"
                : "=l"(acc) : "l"(rt64[j][2]), "l"(win[k][2]), "l"(acc));
            asm("fma.rn.f32x2 %0, %1, %2, %3;"
                : "=l"(acc) : "l"(rt64[j][3]), "l"(win[k][3]), "l"(acc));
            float lo, hi;
            asm("mov.b64 {%0, %1}, %2;" : "=f"(lo), "=f"(hi) : "l"(acc));
            if (j == 0) o.x = lo + hi; else o.y = lo + hi;
        }
        *(float2*)op = o;
        op += (size_t)Hh * Ww;

        if (d < ND - 1) {
            const int slot = (d + 1) & 1;
            if (rb_off >= 0) {
                const unsigned char* base = smem + rb_off;
#pragma unroll
                for (int p = 0; p < 4; p++)
                    win[slot][p] = *(const unsigned long long*)(base + 8 * p);
            } else {
#pragma unroll
                for (int p = 0; p < 4; p++)
                    win[slot][p] = 0ull;
            }
            rb_off -= PSTRIDE;
        }
    }
}

// ---------------------------------------------------------------------------
// Concat: CTA per (h, grp) covering d = 4*grp .. 4*grp+3.
// Since d0 % 4 == 0: shift s = t (compile-time) and chunk offset a = grp
// (CTA-uniform) -> the SAME two tgt float4 loads serve all 4 d-planes, and
// ref is loaded once per 4 planes. 120 threads: half = t>=60 picks channel
// parity, q = chunk index.
// ---------------------------------------------------------------------------
__device__ __forceinline__ void cat_part(
    int h, int grp, int t,
    const float* __restrict__ rc, const float* __restrict__ tc,
    float* __restrict__ out)
{
    if (t >= 120) return;
    const int half = (t >= 60) ? 1 : 0;
    const int q    = t - 60 * half;
    const int wb   = 4 * q;
    const int d0   = 4 * grp;
    const size_t hw = (size_t)Hh * Ww;

#pragma unroll
    for (int i = 0; i < 12; i++) {
        const int cc = half + 2 * i;      // 0..23
        float* ob = out + ((size_t)(NG + cc) * ND + d0) * hw + (size_t)h * Ww + wb;

        if (i < 6) {
            // ref channel cc: one load, 4 masked stores (d = d0+t2)
            float4 v = *(const float4*)(rc + ((size_t)cc * Hh + h) * Ww + wb);
#pragma unroll
            for (int t2 = 0; t2 < 4; t2++) {
                const int d = d0 + t2;
                float4 o;
                o.x = (wb + 0 >= d) ? v.x : 0.f;
                o.y = (wb + 1 >= d) ? v.y : 0.f;
                o.z = (wb + 2 >= d) ? v.z : 0.f;
                o.w = (wb + 3 >= d) ? v.w : 0.f;
                *(float4*)(ob + (size_t)t2 * hw) = o;
            }
        } else {
            // tgt channel cc-12: two loads serve 4 shifted stores
            const int ch = cc - NCC;
            const float* row = tc + ((size_t)ch * Hh + h) * Ww;
            const int c1 = q - grp, c0 = q - grp - 1;
            float4 v1 = (c1 >= 0) ? *(const float4*)(row + 4 * c1)
                                  : make_float4(0.f, 0.f, 0.f, 0.f);
            float4 v0 = (c0 >= 0) ? *(const float4*)(row + 4 * c0)
                                  : make_float4(0.f, 0.f, 0.f, 0.f);
#pragma unroll
            for (int t2 = 0; t2 < 4; t2++) {
                float4 o;
                if (t2 == 0)      { o = v1; }
                else if (t2 == 1) { o.x = v0.w; o.y = v1.x; o.z = v1.y; o.w = v1.z; }
                else if (t2 == 2) { o.x = v0.z; o.y = v0.w; o.z = v1.x; o.w = v1.y; }
                else              { o.x = v0.y; o.y = v0.z; o.z = v0.w; o.w = v1.x; }
                *(float4*)(ob + (size_t)t2 * hw) = o;
            }
        }
    }
}

// ---------------------------------------------------------------------------
__global__ void __launch_bounds__(128, 10) fused_kernel(
    const float* __restrict__ refg, const float* __restrict__ tgtg,
    const float* __restrict__ rc,   const float* __restrict__ tc,
    float* __restrict__ out)
{
    __shared__ __align__(16) unsigned char smem[Ww * PSTRIDE];  // 9600B

    const int bx  = blockIdx.x;
    const int tid = threadIdx.x;
    const int qq  = bx / 13;
    const int r   = bx - qq * 13;

    if (r < 10) {
        const int idx = qq * 10 + r;         // 0..5119
        gwc_part(smem, idx / Hh, idx % Hh, tid, refg, tgtg, out);
    } else {
        const int idx = qq * 3 + (r - 10);   // 0..1535
        cat_part(idx % Hh, idx / Hh, tid, rc, tc, out);
    }
}

extern "C" void kernel_launch(void* const* d_in, const int* in_sizes, int n_in,
                              void* d_out, int out_size)
{
    const float* refg = (const float*)d_in[0];  // ref_gwc    [320,128,240]
    const float* tgtg = (const float*)d_in[1];  // tgt_gwc    [320,128,240]
    const float* rc   = (const float*)d_in[2];  // ref_concat [12,128,240]
    const float* tc   = (const float*)d_in[3];  // tgt_concat [12,128,240]
    float* out = (float*)d_out;                 // [64,48,128,240]

    fused_kernel<<<TOTAL_CTAS, 128>>>(refg, tgtg, rc, tc, out);
}